// round 14
// baseline (speedup 1.0000x reference)
#include <cuda_runtime.h>
#include <cuda_bf16.h>
#include <cstddef>

#define NN   50000
#define EE   800000
#define INF  512
#define H1F  256
#define H2F  128
#define NEG  0.2f
#define NBLK 196   // ceil(NN/256)

// ---------------- scratch (device globals) ----------------
__device__ int   g_is64;
__device__ int   g_cnt[NN];
__device__ int   g_cur[NN];
__device__ int   g_rowptr[NN + 1];
__device__ int   g_bsum[NBLK];
__device__ float g_dinv[NN];
__device__ int   g_csrc[EE];
__device__ float g_ccoef[EE];
__device__ float g_W1T[H1F * INF];   // W1^T, tf32-rounded, [N][K]
__device__ float g_W2T[H2F * H1F];   // W2^T, tf32-rounded, [N][K]
__device__ float g_H1[NN * H1F];
__device__ float g_A1[NN * H1F];     // tf32-rounded activations
__device__ float g_H2[NN * H2F];

__device__ __forceinline__ unsigned rna(float x) {
    unsigned r;
    asm("cvt.rna.tf32.f32 %0, %1;" : "=r"(r) : "f"(x));
    return r;
}

// ---------------- zero + edge dtype detect (merged) ----------------
__global__ void k_zerodet(const int* __restrict__ w) {
    int i = blockIdx.x * blockDim.x + threadIdx.x;
    if (i < NN) { g_cnt[i] = 0; g_cur[i] = 0; }
    if (blockIdx.x == 0) {
        __shared__ int nz;
        if (threadIdx.x == 0) nz = 0;
        __syncthreads();
        for (int j = threadIdx.x; j < 1024; j += blockDim.x)
            if (w[2 * j + 1] != 0) atomicOr(&nz, 1);
        __syncthreads();
        if (threadIdx.x == 0) g_is64 = (nz == 0) ? 1 : 0;
    }
}

__global__ void k_hist(const int* __restrict__ w) {
    int e = blockIdx.x * blockDim.x + threadIdx.x;
    if (e >= EE) return;
    int d = g_is64 ? w[2 * EE + 2 * e] : w[EE + e];
    atomicAdd(&g_cnt[d], 1);
}

// transpose + tf32-round both weight matrices (tiny)
__global__ void k_wt(const float* __restrict__ W1, const float* __restrict__ W2) {
    int i = blockIdx.x * blockDim.x + threadIdx.x;
    if (i < INF * H1F) {
        int n = i / INF, k = i % INF;
        g_W1T[i] = __uint_as_float(rna(W1[(size_t)k * H1F + n]));
    }
    if (i < H1F * H2F) {
        int n = i / H1F, k = i % H1F;
        g_W2T[i] = __uint_as_float(rna(W2[(size_t)k * H2F + n]));
    }
}

__global__ void k_scan1() {
    __shared__ int sh[256];
    int tid = threadIdx.x;
    int i = blockIdx.x * 256 + tid;
    sh[tid] = (i < NN) ? g_cnt[i] : 0;
    __syncthreads();
    for (int ofs = 128; ofs > 0; ofs >>= 1) {
        if (tid < ofs) sh[tid] += sh[tid + ofs];
        __syncthreads();
    }
    if (tid == 0) g_bsum[blockIdx.x] = sh[0];
}

__global__ void k_scan23() {
    __shared__ int sh[256];
    __shared__ int boff_sh;
    int tid = threadIdx.x;
    int b = blockIdx.x;
    sh[tid] = (tid < b) ? g_bsum[tid] : 0;
    __syncthreads();
    for (int ofs = 128; ofs > 0; ofs >>= 1) {
        if (tid < ofs) sh[tid] += sh[tid + ofs];
        __syncthreads();
    }
    if (tid == 0) boff_sh = sh[0];
    __syncthreads();
    int boff = boff_sh;
    __syncthreads();
    int i = b * 256 + tid;
    int v = (i < NN) ? g_cnt[i] : 0;
    sh[tid] = v;
    __syncthreads();
    for (int ofs = 1; ofs < 256; ofs <<= 1) {
        int t = (tid >= ofs) ? sh[tid - ofs] : 0;
        __syncthreads();
        sh[tid] += t;
        __syncthreads();
    }
    if (i < NN) {
        g_rowptr[i] = sh[tid] - v + boff;
        g_dinv[i] = rsqrtf((float)v + 1.0f);
    }
    if (b == 0 && tid == 0) g_rowptr[NN] = EE;
}

__global__ void k_place(const int* __restrict__ w) {
    int e = blockIdx.x * blockDim.x + threadIdx.x;
    if (e >= EE) return;
    int s, d;
    if (g_is64) { s = w[2 * e]; d = w[2 * EE + 2 * e]; }
    else        { s = w[e];     d = w[EE + e]; }
    float cf = g_dinv[s] * g_dinv[d];
    int pos = g_rowptr[d] + atomicAdd(&g_cur[d], 1);
    g_csrc[pos]  = s;
    g_ccoef[pos] = cf;
}

// ---------------- TF32 GEMM: 3-stage cp.async, 128x128 tile, XOR-swizzled smem ----------------
// A: [M][K] k-major. B: WT [N][K] k-major pre-rounded tf32.
// smem row = 32 floats = 8 granules of 16B; granule index g ^= (row & 7).
#define TILE_ELEMS (128 * 32)                 // 4096 floats per operand per stage
#define NSTAGE 3
#define GEMM_SMEM (NSTAGE * 2 * TILE_ELEMS * 4)   // 98304 B

__device__ __forceinline__ void cp16(void* dst_smem, const void* src, int sz) {
    unsigned d = (unsigned)__cvta_generic_to_shared(dst_smem);
    asm volatile("cp.async.cg.shared.global [%0], [%1], 16, %2;\n"
                 :: "r"(d), "l"(src), "r"(sz));
}
__device__ __forceinline__ void cp_commit() {
    asm volatile("cp.async.commit_group;\n");
}
__device__ __forceinline__ void cp_wait1() {
    asm volatile("cp.async.wait_group 1;\n");
}
__device__ __forceinline__ void ldsm4(unsigned& r0, unsigned& r1, unsigned& r2, unsigned& r3,
                                      const float* p) {
    unsigned a = (unsigned)__cvta_generic_to_shared(p);
    asm volatile("ldmatrix.sync.aligned.m8n8.x4.shared.b16 {%0,%1,%2,%3}, [%4];"
                 : "=r"(r0), "=r"(r1), "=r"(r2), "=r"(r3) : "r"(a));
}

__device__ __forceinline__ void mma_tf32(float& c0, float& c1, float& c2, float& c3,
                                         unsigned a0, unsigned a1, unsigned a2, unsigned a3,
                                         unsigned b0, unsigned b1) {
    asm volatile(
        "mma.sync.aligned.m16n8k8.row.col.f32.tf32.tf32.f32 "
        "{%0,%1,%2,%3},{%4,%5,%6,%7},{%8,%9},{%0,%1,%2,%3};"
        : "+f"(c0), "+f"(c1), "+f"(c2), "+f"(c3)
        : "r"(a0), "r"(a1), "r"(a2), "r"(a3), "r"(b0), "r"(b1));
}

template <bool CVT_A>
__device__ __forceinline__ void gemm_body(const float* __restrict__ A,
                                          const float* __restrict__ WT,
                                          float* __restrict__ C,
                                          int M, int N, int K) {
    extern __shared__ float sm[];
    float* As = sm;                               // [NSTAGE][128][32] swizzled
    float* Bs = sm + NSTAGE * TILE_ELEMS;         // [NSTAGE][128][32] swizzled (n-major)

    const int tid  = threadIdx.x;
    const int warp = tid >> 5;
    const int lane = tid & 31;
    const int wm = warp & 3;
    const int wn = warp >> 2;
    const int g  = lane >> 2;
    const int tg = lane & 3;
    const int row0 = blockIdx.y * 128;
    const int col0 = blockIdx.x * 128;

    // fill indices: each thread covers 4 rows (stride 32), one 16B granule per row
    const int fr = tid >> 3;            // 0..31
    const int fg = tid & 7;             // granule 0..7

    // per-lane fragment rows
    int arow[2], brow[4];
#pragma unroll
    for (int mi = 0; mi < 2; mi++)
        arow[mi] = wm * 32 + mi * 16 + ((lane >> 3) & 1) * 8 + (lane & 7);
#pragma unroll
    for (int p = 0; p < 4; p++)
        brow[p] = wn * 64 + p * 16 + ((lane >> 4) & 1) * 8 + (lane & 7);
    const int aghi = lane >> 4;         // 0/1 granule offset within k-tile
    const int bghi = (lane >> 3) & 1;

    float c[2][8][4];
#pragma unroll
    for (int mi = 0; mi < 2; mi++)
#pragma unroll
        for (int ni = 0; ni < 8; ni++)
#pragma unroll
            for (int q = 0; q < 4; q++) c[mi][ni][q] = 0.0f;

    const int KT = K >> 5;

    auto fill = [&](int s, int kt) {
        float* as = As + s * TILE_ELEMS;
        float* bs = Bs + s * TILE_ELEMS;
#pragma unroll
        for (int it = 0; it < 4; it++) {
            int r = fr + it * 32;
            int sg = fg ^ (r & 7);
            int sz = (row0 + r < M) ? 16 : 0;
            cp16(as + r * 32 + sg * 4, A + (size_t)(row0 + r) * K + kt + fg * 4, sz);
        }
#pragma unroll
        for (int it = 0; it < 4; it++) {
            int r = fr + it * 32;
            int sg = fg ^ (r & 7);
            cp16(bs + r * 32 + sg * 4, WT + (size_t)(col0 + r) * K + kt + fg * 4, 16);
        }
    };

    fill(0, 0);
    cp_commit();
    if (KT > 1) fill(1, 32);
    cp_commit();

    for (int kti = 0; kti < KT; kti++) {
        cp_wait1();
        __syncthreads();
        {
            int nx = kti + 2;
            if (nx < KT) fill(nx % NSTAGE, nx * 32);
            cp_commit();
        }

        const float* as = As + (kti % NSTAGE) * TILE_ELEMS;
        const float* bs = Bs + (kti % NSTAGE) * TILE_ELEMS;
#pragma unroll
        for (int ks = 0; ks < 4; ks++) {
            unsigned a[2][4], b[8][2];
#pragma unroll
            for (int mi = 0; mi < 2; mi++) {
                int r = arow[mi];
                int gr = (2 * ks + aghi) ^ (r & 7);
                ldsm4(a[mi][0], a[mi][1], a[mi][2], a[mi][3], as + r * 32 + gr * 4);
                if (CVT_A) {
#pragma unroll
                    for (int q = 0; q < 4; q++)
                        a[mi][q] = rna(__uint_as_float(a[mi][q]));
                }
            }
#pragma unroll
            for (int p = 0; p < 4; p++) {
                int r = brow[p];
                int gr = (2 * ks + bghi) ^ (r & 7);
                ldsm4(b[2 * p][0], b[2 * p][1], b[2 * p + 1][0], b[2 * p + 1][1],
                      bs + r * 32 + gr * 4);
            }
#pragma unroll
            for (int mi = 0; mi < 2; mi++)
#pragma unroll
                for (int ni = 0; ni < 8; ni++)
                    mma_tf32(c[mi][ni][0], c[mi][ni][1], c[mi][ni][2], c[mi][ni][3],
                             a[mi][0], a[mi][1], a[mi][2], a[mi][3],
                             b[ni][0], b[ni][1]);
        }
        __syncthreads();
    }

#pragma unroll
    for (int mi = 0; mi < 2; mi++) {
        int r0 = row0 + wm * 32 + mi * 16 + g;
#pragma unroll
        for (int ni = 0; ni < 8; ni++) {
            int cc = col0 + wn * 64 + ni * 8 + 2 * tg;
            if (r0 < M) {
                C[(size_t)r0 * N + cc]     = c[mi][ni][0];
                C[(size_t)r0 * N + cc + 1] = c[mi][ni][1];
            }
            if (r0 + 8 < M) {
                C[(size_t)(r0 + 8) * N + cc]     = c[mi][ni][2];
                C[(size_t)(r0 + 8) * N + cc + 1] = c[mi][ni][3];
            }
        }
    }
}

__global__ void k_gemm1(const float* __restrict__ X) {
    gemm_body<true>(X, g_W1T, g_H1, NN, H1F, INF);
}
__global__ void k_gemm2() {
    gemm_body<false>(g_A1, g_W2T, g_H2, NN, H2F, H1F);
}

// ---------------- fused CSR aggregate + self-loop + bias + leakyReLU (float4) ----------------
// one block per node, C/4 threads, each thread owns 4 channels.
template <int C, bool ROUND>
__device__ __forceinline__ void agg_body(const float* __restrict__ H,
                                         const float* __restrict__ bias,
                                         float* __restrict__ Out) {
    const int CH = C / 4;
    const int n   = blockIdx.x;
    const int tid = threadIdx.x;
    const int beg = g_rowptr[n];
    const int end = g_rowptr[n + 1];
    const float4* H4 = (const float4*)H;

    float dv = g_dinv[n];
    float s = dv * dv;
    float4 h = __ldg(&H4[(size_t)n * CH + tid]);
    float4 a0 = make_float4(h.x * s, h.y * s, h.z * s, h.w * s);
    float4 a1 = make_float4(0.f, 0.f, 0.f, 0.f);
    float4 a2 = a1, a3 = a1;

    int j = beg;
    for (; j + 4 <= end; j += 4) {
        int s0 = __ldg(&g_csrc[j]);
        int s1 = __ldg(&g_csrc[j + 1]);
        int s2 = __ldg(&g_csrc[j + 2]);
        int s3 = __ldg(&g_csrc[j + 3]);
        float c0 = __ldg(&g_ccoef[j]);
        float c1 = __ldg(&g_ccoef[j + 1]);
        float c2 = __ldg(&g_ccoef[j + 2]);
        float c3 = __ldg(&g_ccoef[j + 3]);
        float4 v0 = __ldg(&H4[(size_t)s0 * CH + tid]);
        float4 v1 = __ldg(&H4[(size_t)s1 * CH + tid]);
        float4 v2 = __ldg(&H4[(size_t)s2 * CH + tid]);
        float4 v3 = __ldg(&H4[(size_t)s3 * CH + tid]);
        a0.x += c0 * v0.x; a0.y += c0 * v0.y; a0.z += c0 * v0.z; a0.w += c0 * v0.w;
        a1.x += c1 * v1.x; a1.y += c1 * v1.y; a1.z += c1 * v1.z; a1.w += c1 * v1.w;
        a2.x += c2 * v2.x; a2.y += c2 * v2.y; a2.z += c2 * v2.z; a2.w += c2 * v2.w;
        a3.x += c3 * v3.x; a3.y += c3 * v3.y; a3.z += c3 * v3.z; a3.w += c3 * v3.w;
    }
    for (; j < end; j++) {
        float cf = __ldg(&g_ccoef[j]);
        float4 v = __ldg(&H4[(size_t)__ldg(&g_csrc[j]) * CH + tid]);
        a0.x += cf * v.x; a0.y += cf * v.y; a0.z += cf * v.z; a0.w += cf * v.w;
    }

    float4 bb = __ldg(&((const float4*)bias)[tid]);
    float4 r;
    r.x = (a0.x + a1.x) + (a2.x + a3.x) + bb.x;
    r.y = (a0.y + a1.y) + (a2.y + a3.y) + bb.y;
    r.z = (a0.z + a1.z) + (a2.z + a3.z) + bb.z;
    r.w = (a0.w + a1.w) + (a2.w + a3.w) + bb.w;
    r.x = r.x > 0.f ? r.x : r.x * NEG;
    r.y = r.y > 0.f ? r.y : r.y * NEG;
    r.z = r.z > 0.f ? r.z : r.z * NEG;
    r.w = r.w > 0.f ? r.w : r.w * NEG;
    if (ROUND) {
        r.x = __uint_as_float(rna(r.x));
        r.y = __uint_as_float(rna(r.y));
        r.z = __uint_as_float(rna(r.z));
        r.w = __uint_as_float(rna(r.w));
    }
    ((float4*)Out)[(size_t)n * CH + tid] = r;
}

__global__ void k_agg1(const float* __restrict__ b) { agg_body<H1F, true>(g_H1, b, g_A1); }
__global__ void k_agg2(const float* __restrict__ b, float* __restrict__ out) {
    agg_body<H2F, false>(g_H2, b, out);
}

// ---------------- launch (single stream; gemm1 at launch index 3 for ncu) ----------------
extern "C" void kernel_launch(void* const* d_in, const int* in_sizes, int n_in,
                              void* d_out, int out_size) {
    const float* X  = (const float*)d_in[0];
    const int*   ew = (const int*)d_in[1];
    const float* W1 = (const float*)d_in[2];
    const float* b1 = (const float*)d_in[3];
    const float* W2 = (const float*)d_in[4];
    const float* b2 = (const float*)d_in[5];
    float* out = (float*)d_out;

    cudaFuncSetAttribute(k_gemm1, cudaFuncAttributeMaxDynamicSharedMemorySize, GEMM_SMEM);
    cudaFuncSetAttribute(k_gemm2, cudaFuncAttributeMaxDynamicSharedMemorySize, GEMM_SMEM);

    const int T = 256;
    k_zerodet<<<NBLK, T>>>(ew);                      // 0
    k_hist<<<(EE + T - 1) / T, T>>>(ew);             // 1
    k_wt<<<(INF * H1F + T - 1) / T, T>>>(W1, W2);    // 2

    dim3 g1(H1F / 128, (NN + 127) / 128);
    k_gemm1<<<g1, 256, GEMM_SMEM>>>(X);              // 3  <- ncu capture point

    k_scan1<<<NBLK, T>>>();                          // 4
    k_scan23<<<NBLK, T>>>();                         // 5
    k_place<<<(EE + T - 1) / T, T>>>(ew);            // 6

    k_agg1<<<NN, H1F / 4>>>(b1);                     // 7

    dim3 g2(H2F / 128, (NN + 127) / 128);
    k_gemm2<<<g2, 256, GEMM_SMEM>>>();               // 8
    k_agg2<<<NN, H2F / 4>>>(b2, out);                // 9
}

// round 15
// speedup vs baseline: 1.0002x; 1.0002x over previous
#include <cuda_runtime.h>
#include <cuda_bf16.h>
#include <cstddef>

#define NN   50000
#define EE   800000
#define INF  512
#define H1F  256
#define H2F  128
#define NEG  0.2f
#define NBLK 196   // ceil(NN/256)

// ---------------- scratch (device globals) ----------------
__device__ int   g_is64;
__device__ int   g_cnt[NN];
__device__ int   g_cur[NN];
__device__ int   g_rowptr[NN + 1];
__device__ int   g_bsum[NBLK];
__device__ float g_dinv[NN];
__device__ int   g_csrc[EE];
__device__ float g_ccoef[EE];
__device__ float g_W1T[H1F * INF];   // W1^T, tf32-rounded, [N][K]
__device__ float g_W2T[H2F * H1F];   // W2^T, tf32-rounded, [N][K]
__device__ float g_H1[NN * H1F];
__device__ float g_A1[NN * H1F];     // tf32-rounded activations
__device__ float g_H2[NN * H2F];

__device__ __forceinline__ unsigned rna(float x) {
    unsigned r;
    asm("cvt.rna.tf32.f32 %0, %1;" : "=r"(r) : "f"(x));
    return r;
}

// ---------------- zero + edge dtype detect (merged) ----------------
__global__ void k_zerodet(const int* __restrict__ w) {
    int i = blockIdx.x * blockDim.x + threadIdx.x;
    if (i < NN) { g_cnt[i] = 0; g_cur[i] = 0; }
    if (blockIdx.x == 0) {
        __shared__ int nz;
        if (threadIdx.x == 0) nz = 0;
        __syncthreads();
        for (int j = threadIdx.x; j < 1024; j += blockDim.x)
            if (w[2 * j + 1] != 0) atomicOr(&nz, 1);
        __syncthreads();
        if (threadIdx.x == 0) g_is64 = (nz == 0) ? 1 : 0;
    }
}

__global__ void k_hist(const int* __restrict__ w) {
    int e = blockIdx.x * blockDim.x + threadIdx.x;
    if (e >= EE) return;
    int d = g_is64 ? w[2 * EE + 2 * e] : w[EE + e];
    atomicAdd(&g_cnt[d], 1);
}

// transpose + tf32-round both weight matrices (tiny)
__global__ void k_wt(const float* __restrict__ W1, const float* __restrict__ W2) {
    int i = blockIdx.x * blockDim.x + threadIdx.x;
    if (i < INF * H1F) {
        int n = i / INF, k = i % INF;
        g_W1T[i] = __uint_as_float(rna(W1[(size_t)k * H1F + n]));
    }
    if (i < H1F * H2F) {
        int n = i / H1F, k = i % H1F;
        g_W2T[i] = __uint_as_float(rna(W2[(size_t)k * H2F + n]));
    }
}

__global__ void k_scan1() {
    __shared__ int sh[256];
    int tid = threadIdx.x;
    int i = blockIdx.x * 256 + tid;
    sh[tid] = (i < NN) ? g_cnt[i] : 0;
    __syncthreads();
    for (int ofs = 128; ofs > 0; ofs >>= 1) {
        if (tid < ofs) sh[tid] += sh[tid + ofs];
        __syncthreads();
    }
    if (tid == 0) g_bsum[blockIdx.x] = sh[0];
}

__global__ void k_scan23() {
    __shared__ int sh[256];
    __shared__ int boff_sh;
    int tid = threadIdx.x;
    int b = blockIdx.x;
    sh[tid] = (tid < b) ? g_bsum[tid] : 0;
    __syncthreads();
    for (int ofs = 128; ofs > 0; ofs >>= 1) {
        if (tid < ofs) sh[tid] += sh[tid + ofs];
        __syncthreads();
    }
    if (tid == 0) boff_sh = sh[0];
    __syncthreads();
    int boff = boff_sh;
    __syncthreads();
    int i = b * 256 + tid;
    int v = (i < NN) ? g_cnt[i] : 0;
    sh[tid] = v;
    __syncthreads();
    for (int ofs = 1; ofs < 256; ofs <<= 1) {
        int t = (tid >= ofs) ? sh[tid - ofs] : 0;
        __syncthreads();
        sh[tid] += t;
        __syncthreads();
    }
    if (i < NN) {
        g_rowptr[i] = sh[tid] - v + boff;
        g_dinv[i] = rsqrtf((float)v + 1.0f);
    }
    if (b == 0 && tid == 0) g_rowptr[NN] = EE;
}

__global__ void k_place(const int* __restrict__ w) {
    int e = blockIdx.x * blockDim.x + threadIdx.x;
    if (e >= EE) return;
    int s, d;
    if (g_is64) { s = w[2 * e]; d = w[2 * EE + 2 * e]; }
    else        { s = w[e];     d = w[EE + e]; }
    float cf = g_dinv[s] * g_dinv[d];
    int pos = g_rowptr[d] + atomicAdd(&g_cur[d], 1);
    g_csrc[pos]  = s;
    g_ccoef[pos] = cf;
}

// ---------------- TF32 GEMM: 3-stage cp.async, 128x128 tile, XOR-swizzled smem ----------------
// A: [M][K] k-major. B: WT [N][K] k-major pre-rounded tf32.
// smem row = 32 floats = 8 granules of 16B; granule index g ^= (row & 7).
#define TILE_ELEMS (128 * 32)                 // 4096 floats per operand per stage
#define NSTAGE 3
#define GEMM_SMEM (NSTAGE * 2 * TILE_ELEMS * 4)   // 98304 B

__device__ __forceinline__ void cp16(void* dst_smem, const void* src, int sz) {
    unsigned d = (unsigned)__cvta_generic_to_shared(dst_smem);
    asm volatile("cp.async.cg.shared.global [%0], [%1], 16, %2;\n"
                 :: "r"(d), "l"(src), "r"(sz));
}
__device__ __forceinline__ void cp_commit() {
    asm volatile("cp.async.commit_group;\n");
}
__device__ __forceinline__ void cp_wait1() {
    asm volatile("cp.async.wait_group 1;\n");
}
__device__ __forceinline__ void ldsm4(unsigned& r0, unsigned& r1, unsigned& r2, unsigned& r3,
                                      const float* p) {
    unsigned a = (unsigned)__cvta_generic_to_shared(p);
    asm volatile("ldmatrix.sync.aligned.m8n8.x4.shared.b16 {%0,%1,%2,%3}, [%4];"
                 : "=r"(r0), "=r"(r1), "=r"(r2), "=r"(r3) : "r"(a));
}

__device__ __forceinline__ void mma_tf32(float& c0, float& c1, float& c2, float& c3,
                                         unsigned a0, unsigned a1, unsigned a2, unsigned a3,
                                         unsigned b0, unsigned b1) {
    asm volatile(
        "mma.sync.aligned.m16n8k8.row.col.f32.tf32.tf32.f32 "
        "{%0,%1,%2,%3},{%4,%5,%6,%7},{%8,%9},{%0,%1,%2,%3};"
        : "+f"(c0), "+f"(c1), "+f"(c2), "+f"(c3)
        : "r"(a0), "r"(a1), "r"(a2), "r"(a3), "r"(b0), "r"(b1));
}

template <bool CVT_A>
__device__ __forceinline__ void gemm_body(const float* __restrict__ A,
                                          const float* __restrict__ WT,
                                          float* __restrict__ C,
                                          int M, int N, int K) {
    extern __shared__ float sm[];
    float* As = sm;                               // [NSTAGE][128][32] swizzled
    float* Bs = sm + NSTAGE * TILE_ELEMS;         // [NSTAGE][128][32] swizzled (n-major)

    const int tid  = threadIdx.x;
    const int warp = tid >> 5;
    const int lane = tid & 31;
    const int wm = warp & 3;
    const int wn = warp >> 2;
    const int g  = lane >> 2;
    const int tg = lane & 3;
    const int row0 = blockIdx.y * 128;
    const int col0 = blockIdx.x * 128;

    // fill indices: each thread covers 4 rows (stride 32), one 16B granule per row
    const int fr = tid >> 3;            // 0..31
    const int fg = tid & 7;             // granule 0..7

    // per-lane fragment rows
    int arow[2], brow[4];
#pragma unroll
    for (int mi = 0; mi < 2; mi++)
        arow[mi] = wm * 32 + mi * 16 + ((lane >> 3) & 1) * 8 + (lane & 7);
#pragma unroll
    for (int p = 0; p < 4; p++)
        brow[p] = wn * 64 + p * 16 + ((lane >> 4) & 1) * 8 + (lane & 7);
    const int aghi = lane >> 4;         // 0/1 granule offset within k-tile
    const int bghi = (lane >> 3) & 1;

    float c[2][8][4];
#pragma unroll
    for (int mi = 0; mi < 2; mi++)
#pragma unroll
        for (int ni = 0; ni < 8; ni++)
#pragma unroll
            for (int q = 0; q < 4; q++) c[mi][ni][q] = 0.0f;

    const int KT = K >> 5;

    auto fill = [&](int s, int kt) {
        float* as = As + s * TILE_ELEMS;
        float* bs = Bs + s * TILE_ELEMS;
#pragma unroll
        for (int it = 0; it < 4; it++) {
            int r = fr + it * 32;
            int sg = fg ^ (r & 7);
            int sz = (row0 + r < M) ? 16 : 0;
            cp16(as + r * 32 + sg * 4, A + (size_t)(row0 + r) * K + kt + fg * 4, sz);
        }
#pragma unroll
        for (int it = 0; it < 4; it++) {
            int r = fr + it * 32;
            int sg = fg ^ (r & 7);
            cp16(bs + r * 32 + sg * 4, WT + (size_t)(col0 + r) * K + kt + fg * 4, 16);
        }
    };

    fill(0, 0);
    cp_commit();
    if (KT > 1) fill(1, 32);
    cp_commit();

    for (int kti = 0; kti < KT; kti++) {
        cp_wait1();
        __syncthreads();
        {
            int nx = kti + 2;
            if (nx < KT) fill(nx % NSTAGE, nx * 32);
            cp_commit();
        }

        const float* as = As + (kti % NSTAGE) * TILE_ELEMS;
        const float* bs = Bs + (kti % NSTAGE) * TILE_ELEMS;
#pragma unroll
        for (int ks = 0; ks < 4; ks++) {
            unsigned a[2][4], b[8][2];
#pragma unroll
            for (int mi = 0; mi < 2; mi++) {
                int r = arow[mi];
                int gr = (2 * ks + aghi) ^ (r & 7);
                ldsm4(a[mi][0], a[mi][1], a[mi][2], a[mi][3], as + r * 32 + gr * 4);
                if (CVT_A) {
#pragma unroll
                    for (int q = 0; q < 4; q++)
                        a[mi][q] = rna(__uint_as_float(a[mi][q]));
                }
            }
#pragma unroll
            for (int p = 0; p < 4; p++) {
                int r = brow[p];
                int gr = (2 * ks + bghi) ^ (r & 7);
                ldsm4(b[2 * p][0], b[2 * p][1], b[2 * p + 1][0], b[2 * p + 1][1],
                      bs + r * 32 + gr * 4);
            }
#pragma unroll
            for (int mi = 0; mi < 2; mi++)
#pragma unroll
                for (int ni = 0; ni < 8; ni++)
                    mma_tf32(c[mi][ni][0], c[mi][ni][1], c[mi][ni][2], c[mi][ni][3],
                             a[mi][0], a[mi][1], a[mi][2], a[mi][3],
                             b[ni][0], b[ni][1]);
        }
        __syncthreads();
    }

#pragma unroll
    for (int mi = 0; mi < 2; mi++) {
        int r0 = row0 + wm * 32 + mi * 16 + g;
#pragma unroll
        for (int ni = 0; ni < 8; ni++) {
            int cc = col0 + wn * 64 + ni * 8 + 2 * tg;
            if (r0 < M) {
                C[(size_t)r0 * N + cc]     = c[mi][ni][0];
                C[(size_t)r0 * N + cc + 1] = c[mi][ni][1];
            }
            if (r0 + 8 < M) {
                C[(size_t)(r0 + 8) * N + cc]     = c[mi][ni][2];
                C[(size_t)(r0 + 8) * N + cc + 1] = c[mi][ni][3];
            }
        }
    }
}

__global__ void k_gemm1(const float* __restrict__ X) {
    gemm_body<true>(X, g_W1T, g_H1, NN, H1F, INF);
}
__global__ void k_gemm2() {
    gemm_body<false>(g_A1, g_W2T, g_H2, NN, H2F, H1F);
}

// ---------------- fused CSR aggregate + self-loop + bias + leakyReLU (float4) ----------------
// one block per node, C/4 threads, each thread owns 4 channels.
template <int C, bool ROUND>
__device__ __forceinline__ void agg_body(const float* __restrict__ H,
                                         const float* __restrict__ bias,
                                         float* __restrict__ Out) {
    const int CH = C / 4;
    const int n   = blockIdx.x;
    const int tid = threadIdx.x;
    const int beg = g_rowptr[n];
    const int end = g_rowptr[n + 1];
    const float4* H4 = (const float4*)H;

    float dv = g_dinv[n];
    float s = dv * dv;
    float4 h = __ldg(&H4[(size_t)n * CH + tid]);
    float4 a0 = make_float4(h.x * s, h.y * s, h.z * s, h.w * s);
    float4 a1 = make_float4(0.f, 0.f, 0.f, 0.f);
    float4 a2 = a1, a3 = a1;

    int j = beg;
    for (; j + 4 <= end; j += 4) {
        int s0 = __ldg(&g_csrc[j]);
        int s1 = __ldg(&g_csrc[j + 1]);
        int s2 = __ldg(&g_csrc[j + 2]);
        int s3 = __ldg(&g_csrc[j + 3]);
        float c0 = __ldg(&g_ccoef[j]);
        float c1 = __ldg(&g_ccoef[j + 1]);
        float c2 = __ldg(&g_ccoef[j + 2]);
        float c3 = __ldg(&g_ccoef[j + 3]);
        float4 v0 = __ldg(&H4[(size_t)s0 * CH + tid]);
        float4 v1 = __ldg(&H4[(size_t)s1 * CH + tid]);
        float4 v2 = __ldg(&H4[(size_t)s2 * CH + tid]);
        float4 v3 = __ldg(&H4[(size_t)s3 * CH + tid]);
        a0.x += c0 * v0.x; a0.y += c0 * v0.y; a0.z += c0 * v0.z; a0.w += c0 * v0.w;
        a1.x += c1 * v1.x; a1.y += c1 * v1.y; a1.z += c1 * v1.z; a1.w += c1 * v1.w;
        a2.x += c2 * v2.x; a2.y += c2 * v2.y; a2.z += c2 * v2.z; a2.w += c2 * v2.w;
        a3.x += c3 * v3.x; a3.y += c3 * v3.y; a3.z += c3 * v3.z; a3.w += c3 * v3.w;
    }
    for (; j < end; j++) {
        float cf = __ldg(&g_ccoef[j]);
        float4 v = __ldg(&H4[(size_t)__ldg(&g_csrc[j]) * CH + tid]);
        a0.x += cf * v.x; a0.y += cf * v.y; a0.z += cf * v.z; a0.w += cf * v.w;
    }

    float4 bb = __ldg(&((const float4*)bias)[tid]);
    float4 r;
    r.x = (a0.x + a1.x) + (a2.x + a3.x) + bb.x;
    r.y = (a0.y + a1.y) + (a2.y + a3.y) + bb.y;
    r.z = (a0.z + a1.z) + (a2.z + a3.z) + bb.z;
    r.w = (a0.w + a1.w) + (a2.w + a3.w) + bb.w;
    r.x = r.x > 0.f ? r.x : r.x * NEG;
    r.y = r.y > 0.f ? r.y : r.y * NEG;
    r.z = r.z > 0.f ? r.z : r.z * NEG;
    r.w = r.w > 0.f ? r.w : r.w * NEG;
    if (ROUND) {
        r.x = __uint_as_float(rna(r.x));
        r.y = __uint_as_float(rna(r.y));
        r.z = __uint_as_float(rna(r.z));
        r.w = __uint_as_float(rna(r.w));
    }
    ((float4*)Out)[(size_t)n * CH + tid] = r;
}

__global__ void k_agg1(const float* __restrict__ b) { agg_body<H1F, true>(g_H1, b, g_A1); }
__global__ void k_agg2(const float* __restrict__ b, float* __restrict__ out) {
    agg_body<H2F, false>(g_H2, b, out);
}

// ---------------- launch (single stream; gemm1 at launch index 3 for ncu) ----------------
extern "C" void kernel_launch(void* const* d_in, const int* in_sizes, int n_in,
                              void* d_out, int out_size) {
    const float* X  = (const float*)d_in[0];
    const int*   ew = (const int*)d_in[1];
    const float* W1 = (const float*)d_in[2];
    const float* b1 = (const float*)d_in[3];
    const float* W2 = (const float*)d_in[4];
    const float* b2 = (const float*)d_in[5];
    float* out = (float*)d_out;

    cudaFuncSetAttribute(k_gemm1, cudaFuncAttributeMaxDynamicSharedMemorySize, GEMM_SMEM);
    cudaFuncSetAttribute(k_gemm2, cudaFuncAttributeMaxDynamicSharedMemorySize, GEMM_SMEM);

    const int T = 256;
    k_zerodet<<<NBLK, T>>>(ew);                      // 0
    k_hist<<<(EE + T - 1) / T, T>>>(ew);             // 1
    k_wt<<<(INF * H1F + T - 1) / T, T>>>(W1, W2);    // 2

    dim3 g1(H1F / 128, (NN + 127) / 128);
    k_gemm1<<<g1, 256, GEMM_SMEM>>>(X);              // 3  <- ncu capture point

    k_scan1<<<NBLK, T>>>();                          // 4
    k_scan23<<<NBLK, T>>>();                         // 5
    k_place<<<(EE + T - 1) / T, T>>>(ew);            // 6

    k_agg1<<<NN, H1F / 4>>>(b1);                     // 7

    dim3 g2(H2F / 128, (NN + 127) / 128);
    k_gemm2<<<g2, 256, GEMM_SMEM>>>();               // 8
    k_agg2<<<NN, H2F / 4>>>(b2, out);                // 9
}